// round 16
// baseline (speedup 1.0000x reference)
#include <cuda_runtime.h>
#include <math.h>
#include <stdint.h>

#define BATCH 512
#define INDIM 256
#define HIDD  512
#define HID2  256
#define PAT   10

typedef unsigned long long u64;

// -------- scratch (no allocations allowed) --------
__device__ __align__(128) float g_H [BATCH * HIDD];
__device__ __align__(128) float g_H2[BATCH * HID2];
__device__ __align__(128) float g_A [BATCH * HIDD];
__device__ __align__(128) float g_C [BATCH * HIDD];

// ---------- helpers ----------
__device__ __forceinline__ void unpack2(u64 v, float& lo, float& hi) {
    asm("mov.b64 {%0, %1}, %2;" : "=f"(lo), "=f"(hi) : "l"(v));
}
__device__ __forceinline__ u64 ffma2(u64 a, u64 b, u64 c) {
    u64 d; asm("fma.rn.f32x2 %0, %1, %2, %3;" : "=l"(d) : "l"(a), "l"(b), "l"(c)); return d;
}
__device__ __forceinline__ u64 add2(u64 a, u64 b) {
    u64 d; asm("add.rn.f32x2 %0, %1, %2;" : "=l"(d) : "l"(a), "l"(b)); return d;
}
// acc += relu(a2 + c2) * w2  (k-packed halves)
__device__ __forceinline__ void step2(u64& acc, u64 a2, u64 c2, u64 w2) {
    u64 s = add2(a2, c2);
    float2 f = *reinterpret_cast<float2*>(&s);
    f.x = fmaxf(f.x, 0.f);
    f.y = fmaxf(f.y, 0.f);
    u64 r = *reinterpret_cast<u64*>(&f);
    acc = ffma2(r, w2, acc);
}
__device__ __forceinline__ uint32_t smem_u32(const void* p) {
    uint32_t a;
    asm("{ .reg .u64 t; cvta.to.shared.u64 t, %1; cvt.u32.u64 %0, t; }" : "=r"(a) : "l"(p));
    return a;
}
#define CP16(dst, src) \
    asm volatile("cp.async.cg.shared.global [%0], [%1], 16;" :: "r"(dst), "l"(src) : "memory")
#define CPCOMMIT() asm volatile("cp.async.commit_group;" ::: "memory")
#define CPWAIT1()  asm volatile("cp.async.wait_group 1;" ::: "memory")

// ============================================================
// Inner compute slab for 32x32 GEMM groups: 2m x 4n microtile.
// ============================================================
__device__ __forceinline__ void slab_gemm(
    u64 acc[2][4], const float* Xb, const float* Wb, int tym, int txn)
{
#pragma unroll
    for (int k4 = 0; k4 < 32; k4 += 4) {
        ulonglong2 a0 = *(const ulonglong2*)&Xb[(tym +  0) * 36 + k4];
        ulonglong2 a1 = *(const ulonglong2*)&Xb[(tym + 16) * 36 + k4];
        ulonglong2 b0 = *(const ulonglong2*)&Wb[(txn +  0) * 36 + k4];
        ulonglong2 b1 = *(const ulonglong2*)&Wb[(txn +  8) * 36 + k4];
        ulonglong2 b2 = *(const ulonglong2*)&Wb[(txn + 16) * 36 + k4];
        ulonglong2 b3 = *(const ulonglong2*)&Wb[(txn + 24) * 36 + k4];
        acc[0][0] = ffma2(a0.x, b0.x, acc[0][0]); acc[0][0] = ffma2(a0.y, b0.y, acc[0][0]);
        acc[0][1] = ffma2(a0.x, b1.x, acc[0][1]); acc[0][1] = ffma2(a0.y, b1.y, acc[0][1]);
        acc[0][2] = ffma2(a0.x, b2.x, acc[0][2]); acc[0][2] = ffma2(a0.y, b2.y, acc[0][2]);
        acc[0][3] = ffma2(a0.x, b3.x, acc[0][3]); acc[0][3] = ffma2(a0.y, b3.y, acc[0][3]);
        acc[1][0] = ffma2(a1.x, b0.x, acc[1][0]); acc[1][0] = ffma2(a1.y, b0.y, acc[1][0]);
        acc[1][1] = ffma2(a1.x, b1.x, acc[1][1]); acc[1][1] = ffma2(a1.y, b1.y, acc[1][1]);
        acc[1][2] = ffma2(a1.x, b2.x, acc[1][2]); acc[1][2] = ffma2(a1.y, b2.y, acc[1][2]);
        acc[1][3] = ffma2(a1.x, b3.x, acc[1][3]); acc[1][3] = ffma2(a1.y, b3.y, acc[1][3]);
    }
}

// ============================================================
// Launch 1: three x-projections, 32m x 32n tiles, split-K2,
// 256 threads, per-group 3-stage cp.async pipeline (4 chunks of 32).
// smem floats: group g stages at g*6912 (stage 2304: X[32][36],
// W[32][36] @1152); ex at 13824 (1024). Total 14848 = 59392 B.
// mode 0: BN(+b1)+ReLU ; 1: none ; 2: +p0
// ============================================================
__device__ __forceinline__ void gemm32_sk2(
    const float* __restrict__ X, const float* __restrict__ W,
    float* __restrict__ Out, int N, int K, int m0, int n0, int mode,
    const float* __restrict__ p0, const float* __restrict__ p1,
    const float* __restrict__ p2, const float* __restrict__ p3,
    const float* __restrict__ p4, float* dsm)
{
    const int tid = threadIdx.x;
    const int g   = tid >> 7;
    const int t   = tid & 127;
    const int txn = t & 7;
    const int tym = t >> 3;

    float* Gbase = dsm + g * 6912;
    float* ex    = dsm + 13824;
    const int kb  = g * (K >> 1);
    const int NCH = K >> 6;            // chunks of 32 over K/2

    const float* srcb[4];
    uint32_t     dsto[4];
#pragma unroll
    for (int r = 0; r < 4; r++) {
        const int p = t + (r << 7);
        if (p < 256) {
            const int row = p >> 3, pc = p & 7;
            srcb[r] = X + (size_t)(m0 + row) * K + kb + pc * 4;
            dsto[r] = (uint32_t)(row * 36 + pc * 4) * 4u;
        } else {
            const int q = p - 256;
            const int row = q >> 3, pc = q & 7;
            srcb[r] = W + (size_t)(n0 + row) * K + kb + pc * 4;
            dsto[r] = (uint32_t)(1152 + row * 36 + pc * 4) * 4u;
        }
    }
    const uint32_t smb = smem_u32(Gbase);

#define P_ISSUE(c) do {                                   \
        const uint32_t sb = smb + ((c) % 3) * 9216u;      \
        CP16(sb + dsto[0], srcb[0] + (c) * 32);           \
        CP16(sb + dsto[1], srcb[1] + (c) * 32);           \
        CP16(sb + dsto[2], srcb[2] + (c) * 32);           \
        CP16(sb + dsto[3], srcb[3] + (c) * 32);           \
        CPCOMMIT();                                       \
    } while (0)

    P_ISSUE(0);
    P_ISSUE(1);

    u64 acc[2][4];
#pragma unroll
    for (int q = 0; q < 2; q++)
#pragma unroll
        for (int p = 0; p < 4; p++) acc[q][p] = 0ull;

#pragma unroll 1
    for (int c = 0; c < NCH; ++c) {
        CPWAIT1();
        __syncthreads();
        if (c + 2 < NCH) { P_ISSUE(c + 2); } else { CPCOMMIT(); }
        const float* Xb = Gbase + (c % 3) * 2304;
        slab_gemm(acc, Xb, Xb + 1152, tym, txn);
    }
#undef P_ISSUE

    float va[2][4];
#pragma unroll
    for (int q = 0; q < 2; q++)
#pragma unroll
        for (int p = 0; p < 4; p++) {
            float lo, hi; unpack2(acc[q][p], lo, hi);
            va[q][p] = lo + hi;
        }

    if (g == 1) {
        *(float4*)&ex[t * 8]     = make_float4(va[0][0], va[0][1], va[0][2], va[0][3]);
        *(float4*)&ex[t * 8 + 4] = make_float4(va[1][0], va[1][1], va[1][2], va[1][3]);
    }
    __syncthreads();
    if (g == 1) return;
    {
        float4 e0 = *(const float4*)&ex[t * 8];
        float4 e1 = *(const float4*)&ex[t * 8 + 4];
        va[0][0] += e0.x; va[0][1] += e0.y; va[0][2] += e0.z; va[0][3] += e0.w;
        va[1][0] += e1.x; va[1][1] += e1.y; va[1][2] += e1.z; va[1][3] += e1.w;
    }

#pragma unroll
    for (int p = 0; p < 4; p++) {
        const int n = n0 + txn + 8 * p;
        float bias = 0.f, scale = 1.f, off = 0.f;
        if (mode == 0) {
            bias  = p0[n];
            scale = p1[n] * rsqrtf(p4[n] + 1e-5f);
            off   = p2[n] - p3[n] * scale;
        } else if (mode == 2) {
            bias = p0[n];
        }
#pragma unroll
        for (int q = 0; q < 2; q++) {
            float v = va[q][p];
            if (mode == 0)      v = fmaxf(fmaf(v + bias, scale, off), 0.f);
            else if (mode == 2) v = v + bias;
            Out[(size_t)(m0 + tym + 16 * q) * N + n] = v;
        }
    }
}

__global__ __launch_bounds__(256)
void k_proj(const float* __restrict__ x,
            const float* __restrict__ W1, const float* __restrict__ b1,
            const float* __restrict__ gam, const float* __restrict__ bet,
            const float* __restrict__ mean, const float* __restrict__ var,
            const float* __restrict__ Wa, const float* __restrict__ Wb,
            const float* __restrict__ bs1)
{
    extern __shared__ __align__(16) float psm[];
    const int m0 = blockIdx.y * 32;
    const int n0 = blockIdx.x * 32;
    const int z  = blockIdx.z;
    if (z == 0)
        gemm32_sk2(x, W1, g_H, HIDD, INDIM, m0, n0, 0, b1, gam, bet, mean, var, psm);
    else if (z == 1)
        gemm32_sk2(x, Wa, g_A, HIDD, INDIM, m0, n0, 1,
                   nullptr, nullptr, nullptr, nullptr, nullptr, psm);
    else
        gemm32_sk2(x, Wb, g_C, HIDD, INDIM, m0, n0, 2,
                   bs1, nullptr, nullptr, nullptr, nullptr, psm);
}

// ============================================================
// Launch 2: 512 threads = 4 K-groups of 128, split-K4.
// blocks [0,136) = sim 32x32 pair tiles (upper triangle);
// blocks [136,264) = H2 32x32 tiles (K=512).
// Per group: 3-stage cp.async pipeline, 4 chunks of 32 over K/4.
// smem floats: group g stages at g*6912 (stage 2304);
// Wbuf at 27648 (512); ex at 28160 (3*1024). Total 31232 = 124928 B.
// ============================================================
__global__ __launch_bounds__(512)
void k_simh2(const float* __restrict__ W2, const float* __restrict__ b2,
             const float* __restrict__ ws2, const float* __restrict__ bs2p,
             float* __restrict__ out_sim)
{
    extern __shared__ __align__(16) float dsm[];

    const int tid = threadIdx.x;
    const int g   = tid >> 7;          // 0..3
    const int t   = tid & 127;
    const int txn = t & 7;
    const int tym = t >> 3;

    float* Gbase = dsm + g * 6912;
    float* Wbuf  = dsm + 27648;
    float* ex    = dsm + 28160;
    const int kb = g * 128;
    const uint32_t smb = smem_u32(Gbase);

    const bool is_h2 = (blockIdx.x >= 136);

    int m0, n0;
    const float *Xsrc, *Wsrc;
    if (is_h2) {
        const int idx = blockIdx.x - 136;      // 0..127
        m0 = (idx >> 3) * 32;                  // 16 m-tiles
        n0 = (idx & 7) * 32;                   // 8 n-tiles
        Xsrc = g_H; Wsrc = W2;
    } else {
        int rb = blockIdx.x, bi = 0;
        while (rb >= 16 - bi) { rb -= 16 - bi; ++bi; }
        m0 = bi * 32;
        n0 = (bi + rb) * 32;
        Xsrc = g_A; Wsrc = g_C;
    }

    const float* srcb[4];
    uint32_t     dsto[4];
#pragma unroll
    for (int r = 0; r < 4; r++) {
        const int p = t + (r << 7);
        if (p < 256) {
            const int row = p >> 3, pc = p & 7;
            srcb[r] = Xsrc + (size_t)(m0 + row) * HIDD + kb + pc * 4;
            dsto[r] = (uint32_t)(row * 36 + pc * 4) * 4u;
        } else {
            const int q = p - 256;
            const int row = q >> 3, pc = q & 7;
            srcb[r] = Wsrc + (size_t)(n0 + row) * HIDD + kb + pc * 4;
            dsto[r] = (uint32_t)(1152 + row * 36 + pc * 4) * 4u;
        }
    }

#define L_ISSUE(c) do {                                   \
        const uint32_t sb = smb + ((c) % 3) * 9216u;      \
        CP16(sb + dsto[0], srcb[0] + (c) * 32);           \
        CP16(sb + dsto[1], srcb[1] + (c) * 32);           \
        CP16(sb + dsto[2], srcb[2] + (c) * 32);           \
        CP16(sb + dsto[3], srcb[3] + (c) * 32);           \
        CPCOMMIT();                                       \
    } while (0)

    L_ISSUE(0);
    L_ISSUE(1);
    if (!is_h2 && tid < 128)
        *(float4*)&Wbuf[tid * 4] = *(const float4*)(ws2 + tid * 4);

    u64 acc[2][4];
#pragma unroll
    for (int q = 0; q < 2; q++)
#pragma unroll
        for (int p = 0; p < 4; p++) acc[q][p] = 0ull;

#pragma unroll 1
    for (int c = 0; c < 4; ++c) {          // 4 chunks of 32 per group
        CPWAIT1();
        __syncthreads();
        if (c + 2 < 4) { L_ISSUE(c + 2); } else { CPCOMMIT(); }

        const float* Xb = Gbase + (c % 3) * 2304;
        const float* Wb = Xb + 1152;
        if (is_h2) {
            slab_gemm(acc, Xb, Wb, tym, txn);
        } else {
            const float* Wk = Wbuf + kb + c * 32;
#pragma unroll
            for (int k4 = 0; k4 < 32; k4 += 4) {
                ulonglong2 w2  = *(const ulonglong2*)&Wk[k4];
                ulonglong2 aa0 = *(const ulonglong2*)&Xb[(tym +  0) * 36 + k4];
                ulonglong2 aa1 = *(const ulonglong2*)&Xb[(tym + 16) * 36 + k4];
                ulonglong2 cc0 = *(const ulonglong2*)&Wb[(txn +  0) * 36 + k4];
                ulonglong2 cc1 = *(const ulonglong2*)&Wb[(txn +  8) * 36 + k4];
                ulonglong2 cc2 = *(const ulonglong2*)&Wb[(txn + 16) * 36 + k4];
                ulonglong2 cc3 = *(const ulonglong2*)&Wb[(txn + 24) * 36 + k4];
                step2(acc[0][0], aa0.x, cc0.x, w2.x); step2(acc[0][0], aa0.y, cc0.y, w2.y);
                step2(acc[0][1], aa0.x, cc1.x, w2.x); step2(acc[0][1], aa0.y, cc1.y, w2.y);
                step2(acc[0][2], aa0.x, cc2.x, w2.x); step2(acc[0][2], aa0.y, cc2.y, w2.y);
                step2(acc[0][3], aa0.x, cc3.x, w2.x); step2(acc[0][3], aa0.y, cc3.y, w2.y);
                step2(acc[1][0], aa1.x, cc0.x, w2.x); step2(acc[1][0], aa1.y, cc0.y, w2.y);
                step2(acc[1][1], aa1.x, cc1.x, w2.x); step2(acc[1][1], aa1.y, cc1.y, w2.y);
                step2(acc[1][2], aa1.x, cc2.x, w2.x); step2(acc[1][2], aa1.y, cc2.y, w2.y);
                step2(acc[1][3], aa1.x, cc3.x, w2.x); step2(acc[1][3], aa1.y, cc3.y, w2.y);
            }
        }
    }
#undef L_ISSUE

    // ---- reduce halves ----
    float va[2][4];
#pragma unroll
    for (int q = 0; q < 2; q++)
#pragma unroll
        for (int p = 0; p < 4; p++) {
            float lo, hi; unpack2(acc[q][p], lo, hi);
            va[q][p] = lo + hi;
        }

    // ---- single combine: groups 1..3 -> ex, group0 adds ----
    if (g > 0) {
        float* e = ex + (g - 1) * 1024;
        *(float4*)&e[t * 8]     = make_float4(va[0][0], va[0][1], va[0][2], va[0][3]);
        *(float4*)&e[t * 8 + 4] = make_float4(va[1][0], va[1][1], va[1][2], va[1][3]);
    }
    __syncthreads();
    if (g > 0) return;
#pragma unroll
    for (int s = 0; s < 3; s++) {
        const float* e = ex + s * 1024;
        float4 e0 = *(const float4*)&e[t * 8];
        float4 e1 = *(const float4*)&e[t * 8 + 4];
        va[0][0] += e0.x; va[0][1] += e0.y; va[0][2] += e0.z; va[0][3] += e0.w;
        va[1][0] += e1.x; va[1][1] += e1.y; va[1][2] += e1.z; va[1][3] += e1.w;
    }

    if (is_h2) {
#pragma unroll
        for (int p = 0; p < 4; p++) {
            const int n = n0 + txn + 8 * p;
            const float b = b2[n];
#pragma unroll
            for (int q = 0; q < 2; q++) {
                const float v = fmaxf(va[q][p] + b, 0.f);
                g_H2[(size_t)(m0 + tym + 16 * q) * HID2 + n] = v;
            }
        }
    } else {
        const float bs2 = *bs2p;
#pragma unroll
        for (int q = 0; q < 2; q++) {
#pragma unroll
            for (int p = 0; p < 4; p++) {
                const int i = m0 + tym + 16 * q;
                const int j = n0 + txn + 8 * p;
                if (i < j) {
                    const float s = 1.f / (1.f + __expf(-(va[q][p] + bs2)));
                    out_sim[(size_t)i * BATCH + j] = s;
                    out_sim[(size_t)j * BATCH + i] = s;
                } else if (i == j) {
                    out_sim[(size_t)i * BATCH + j] = 0.f;
                }
            }
        }
    }
}

// ============================================================
// Launch 3: scores + softmax (reads g_H2), one warp per row.
// ============================================================
__global__ __launch_bounds__(128)
void k_scores(const float* __restrict__ W3, const float* __restrict__ b3,
              float* __restrict__ out_probs, float* __restrict__ out_scores)
{
    const int warp = threadIdx.x >> 5;
    const int lane = threadIdx.x & 31;
    const int row  = blockIdx.x * 4 + warp;
    const float* h = g_H2 + (size_t)row * HID2;

    float acc[PAT];
#pragma unroll
    for (int p = 0; p < PAT; p++) acc[p] = 0.f;

    for (int k = lane; k < HID2; k += 32) {
        const float hv = h[k];
#pragma unroll
        for (int p = 0; p < PAT; p++) acc[p] += hv * W3[p * HID2 + k];
    }
#pragma unroll
    for (int p = 0; p < PAT; p++) {
#pragma unroll
        for (int off = 16; off; off >>= 1)
            acc[p] += __shfl_xor_sync(0xFFFFFFFFu, acc[p], off);
    }
    if (lane == 0) {
        float s[PAT], e[PAT];
        float mx = -1e30f;
#pragma unroll
        for (int p = 0; p < PAT; p++) { s[p] = acc[p] + b3[p]; mx = fmaxf(mx, s[p]); }
        float sum = 0.f;
#pragma unroll
        for (int p = 0; p < PAT; p++) { e[p] = __expf(s[p] - mx); sum += e[p]; }
        const float inv = 1.f / sum;
#pragma unroll
        for (int p = 0; p < PAT; p++) {
            out_scores[row * PAT + p] = s[p];
            out_probs [row * PAT + p] = e[p] * inv;
        }
    }
}

// ============================================================
extern "C" void kernel_launch(void* const* d_in, const int* in_sizes, int n_in,
                              void* d_out, int out_size)
{
    const float* x    = (const float*)d_in[0];
    const float* W1   = (const float*)d_in[1];
    const float* b1   = (const float*)d_in[2];
    const float* gam  = (const float*)d_in[3];
    const float* bet  = (const float*)d_in[4];
    const float* mean = (const float*)d_in[5];
    const float* var  = (const float*)d_in[6];
    const float* W2   = (const float*)d_in[7];
    const float* b2   = (const float*)d_in[8];
    const float* W3   = (const float*)d_in[9];
    const float* b3   = (const float*)d_in[10];
    const float* Wa   = (const float*)d_in[11];
    const float* Wb   = (const float*)d_in[12];
    const float* bs1  = (const float*)d_in[13];
    const float* ws2  = (const float*)d_in[14];
    const float* bs2  = (const float*)d_in[15];

    float* out        = (float*)d_out;
    float* out_probs  = out;
    float* out_scores = out + BATCH * PAT;
    float* out_sim    = out + 2 * BATCH * PAT;

    static bool attr_done = false;
    if (!attr_done) {
        cudaFuncSetAttribute(k_proj, cudaFuncAttributeMaxDynamicSharedMemorySize,
                             14848 * (int)sizeof(float));
        cudaFuncSetAttribute(k_simh2, cudaFuncAttributeMaxDynamicSharedMemorySize,
                             31232 * (int)sizeof(float));
        attr_done = true;
    }

    // 1) H, A, C projections: 768 CTAs x 256 thr, 32x32 tiles, split-K2
    k_proj<<<dim3(16, 16, 3), 256, 14848 * sizeof(float)>>>(
        x, W1, b1, gam, bet, mean, var, Wa, Wb, bs1);
    // 2) sim (136) + H2 (128) tiles: 512 thr, split-K4, uniform CTAs
    k_simh2<<<264, 512, 31232 * sizeof(float)>>>(W2, b2, ws2, bs2, out_sim);
    // 3) scores + softmax
    k_scores<<<BATCH / 4, 128>>>(W3, b3, out_probs, out_scores);
}

// round 17
// speedup vs baseline: 1.2086x; 1.2086x over previous
#include <cuda_runtime.h>
#include <math.h>
#include <stdint.h>

#define BATCH 512
#define INDIM 256
#define HIDD  512
#define HID2  256
#define PAT   10

typedef unsigned long long u64;

// -------- scratch (no allocations allowed) --------
__device__ __align__(128) float g_H [BATCH * HIDD];
__device__ __align__(128) float g_H2[BATCH * HID2];
__device__ __align__(128) float g_A [BATCH * HIDD];
__device__ __align__(128) float g_C [BATCH * HIDD];

// ---------- helpers ----------
__device__ __forceinline__ void unpack2(u64 v, float& lo, float& hi) {
    asm("mov.b64 {%0, %1}, %2;" : "=f"(lo), "=f"(hi) : "l"(v));
}
__device__ __forceinline__ u64 ffma2(u64 a, u64 b, u64 c) {
    u64 d; asm("fma.rn.f32x2 %0, %1, %2, %3;" : "=l"(d) : "l"(a), "l"(b), "l"(c)); return d;
}
__device__ __forceinline__ u64 add2(u64 a, u64 b) {
    u64 d; asm("add.rn.f32x2 %0, %1, %2;" : "=l"(d) : "l"(a), "l"(b)); return d;
}
// acc += relu(a2 + c2) * w2  (k-packed halves)
__device__ __forceinline__ void step2(u64& acc, u64 a2, u64 c2, u64 w2) {
    u64 s = add2(a2, c2);
    float2 f = *reinterpret_cast<float2*>(&s);
    f.x = fmaxf(f.x, 0.f);
    f.y = fmaxf(f.y, 0.f);
    u64 r = *reinterpret_cast<u64*>(&f);
    acc = ffma2(r, w2, acc);
}
__device__ __forceinline__ uint32_t smem_u32(const void* p) {
    uint32_t a;
    asm("{ .reg .u64 t; cvta.to.shared.u64 t, %1; cvt.u32.u64 %0, t; }" : "=r"(a) : "l"(p));
    return a;
}
#define CP16(dst, src) \
    asm volatile("cp.async.cg.shared.global [%0], [%1], 16;" :: "r"(dst), "l"(src) : "memory")
#define CPCOMMIT() asm volatile("cp.async.commit_group;" ::: "memory")
#define CPWAIT1()  asm volatile("cp.async.wait_group 1;" ::: "memory")

// ============================================================
// k_proj: 64m x 32n tile, split-K2 (256 thr = 2 groups of 128),
// each group a 3-stage cp.async pipeline over its K/2 = 128
// (4 chunks of 32). Microtile 4m x 4n (m=tym+16q, n=txn+8p).
// smem floats: group g stages at g*10368 (stage 3456: X[64][36],
// W[32][36] @2304); ex at 20736 (2048). Total 22784 = 91136 B.
// One end-of-loop combine; group0 does epilogue.
// mode 0: BN(+b1)+ReLU ; 1: none ; 2: +p0
// ============================================================
__device__ __forceinline__ void gemm64_sk2cp(
    const float* __restrict__ X, const float* __restrict__ W,
    float* __restrict__ Out, int N, int K, int m0, int n0, int mode,
    const float* __restrict__ p0, const float* __restrict__ p1,
    const float* __restrict__ p2, const float* __restrict__ p3,
    const float* __restrict__ p4, float* dsm)
{
    const int tid = threadIdx.x;
    const int g   = tid >> 7;
    const int t   = tid & 127;
    const int txn = t & 7;
    const int tym = t >> 3;

    float* Gbase = dsm + g * 10368;
    float* ex    = dsm + 20736;
    const int kb  = g * (K >> 1);
    const int NCH = K >> 6;            // chunks of 32 over K/2 (= 4)

    const float* srcb[6];
    uint32_t     dsto[6];
#pragma unroll
    for (int r = 0; r < 6; r++) {
        const int p = t + (r << 7);
        if (p < 512) {             // X: 64 rows x 8 pieces
            const int row = p >> 3, pc = p & 7;
            srcb[r] = X + (size_t)(m0 + row) * K + kb + pc * 4;
            dsto[r] = (uint32_t)(row * 36 + pc * 4) * 4u;
        } else {                   // W: 32 rows x 8 pieces
            const int q = p - 512;
            const int row = q >> 3, pc = q & 7;
            srcb[r] = W + (size_t)(n0 + row) * K + kb + pc * 4;
            dsto[r] = (uint32_t)(2304 + row * 36 + pc * 4) * 4u;
        }
    }
    const uint32_t smb = smem_u32(Gbase);

#define G_ISSUE(c) do {                                   \
        const uint32_t sb = smb + ((c) % 3) * 13824u;     \
        CP16(sb + dsto[0], srcb[0] + (c) * 32);           \
        CP16(sb + dsto[1], srcb[1] + (c) * 32);           \
        CP16(sb + dsto[2], srcb[2] + (c) * 32);           \
        CP16(sb + dsto[3], srcb[3] + (c) * 32);           \
        CP16(sb + dsto[4], srcb[4] + (c) * 32);           \
        CP16(sb + dsto[5], srcb[5] + (c) * 32);           \
        CPCOMMIT();                                       \
    } while (0)

    G_ISSUE(0);
    G_ISSUE(1);

    u64 acc[4][4];
#pragma unroll
    for (int q = 0; q < 4; q++)
#pragma unroll
        for (int p = 0; p < 4; p++) acc[q][p] = 0ull;

#pragma unroll 1
    for (int c = 0; c < NCH; ++c) {
        CPWAIT1();
        __syncthreads();
        if (c + 2 < NCH) { G_ISSUE(c + 2); } else { CPCOMMIT(); }

        const float* Xb = Gbase + (c % 3) * 3456;
        const float* Wb = Xb + 2304;
#pragma unroll
        for (int k4 = 0; k4 < 32; k4 += 4) {
            ulonglong2 a0 = *(const ulonglong2*)&Xb[(tym +  0) * 36 + k4];
            ulonglong2 a1 = *(const ulonglong2*)&Xb[(tym + 16) * 36 + k4];
            ulonglong2 a2 = *(const ulonglong2*)&Xb[(tym + 32) * 36 + k4];
            ulonglong2 a3 = *(const ulonglong2*)&Xb[(tym + 48) * 36 + k4];
            ulonglong2 b0 = *(const ulonglong2*)&Wb[(txn +  0) * 36 + k4];
            ulonglong2 b1 = *(const ulonglong2*)&Wb[(txn +  8) * 36 + k4];
            ulonglong2 b2 = *(const ulonglong2*)&Wb[(txn + 16) * 36 + k4];
            ulonglong2 b3 = *(const ulonglong2*)&Wb[(txn + 24) * 36 + k4];
            acc[0][0] = ffma2(a0.x, b0.x, acc[0][0]); acc[0][0] = ffma2(a0.y, b0.y, acc[0][0]);
            acc[0][1] = ffma2(a0.x, b1.x, acc[0][1]); acc[0][1] = ffma2(a0.y, b1.y, acc[0][1]);
            acc[0][2] = ffma2(a0.x, b2.x, acc[0][2]); acc[0][2] = ffma2(a0.y, b2.y, acc[0][2]);
            acc[0][3] = ffma2(a0.x, b3.x, acc[0][3]); acc[0][3] = ffma2(a0.y, b3.y, acc[0][3]);
            acc[1][0] = ffma2(a1.x, b0.x, acc[1][0]); acc[1][0] = ffma2(a1.y, b0.y, acc[1][0]);
            acc[1][1] = ffma2(a1.x, b1.x, acc[1][1]); acc[1][1] = ffma2(a1.y, b1.y, acc[1][1]);
            acc[1][2] = ffma2(a1.x, b2.x, acc[1][2]); acc[1][2] = ffma2(a1.y, b2.y, acc[1][2]);
            acc[1][3] = ffma2(a1.x, b3.x, acc[1][3]); acc[1][3] = ffma2(a1.y, b3.y, acc[1][3]);
            acc[2][0] = ffma2(a2.x, b0.x, acc[2][0]); acc[2][0] = ffma2(a2.y, b0.y, acc[2][0]);
            acc[2][1] = ffma2(a2.x, b1.x, acc[2][1]); acc[2][1] = ffma2(a2.y, b1.y, acc[2][1]);
            acc[2][2] = ffma2(a2.x, b2.x, acc[2][2]); acc[2][2] = ffma2(a2.y, b2.y, acc[2][2]);
            acc[2][3] = ffma2(a2.x, b3.x, acc[2][3]); acc[2][3] = ffma2(a2.y, b3.y, acc[2][3]);
            acc[3][0] = ffma2(a3.x, b0.x, acc[3][0]); acc[3][0] = ffma2(a3.y, b0.y, acc[3][0]);
            acc[3][1] = ffma2(a3.x, b1.x, acc[3][1]); acc[3][1] = ffma2(a3.y, b1.y, acc[3][1]);
            acc[3][2] = ffma2(a3.x, b2.x, acc[3][2]); acc[3][2] = ffma2(a3.y, b2.y, acc[3][2]);
            acc[3][3] = ffma2(a3.x, b3.x, acc[3][3]); acc[3][3] = ffma2(a3.y, b3.y, acc[3][3]);
        }
    }
#undef G_ISSUE

    // ---- reduce k-pair halves ----
    float va[4][4];
#pragma unroll
    for (int q = 0; q < 4; q++)
#pragma unroll
        for (int p = 0; p < 4; p++) {
            float lo, hi; unpack2(acc[q][p], lo, hi);
            va[q][p] = lo + hi;
        }

    // ---- single combine: group1 -> ex, group0 adds ----
    if (g == 1) {
#pragma unroll
        for (int q = 0; q < 4; q++)
#pragma unroll
            for (int p = 0; p < 4; p++)
                ex[(tym + 16 * q) * 32 + txn + 8 * p] = va[q][p];
    }
    __syncthreads();
    if (g == 1) return;
#pragma unroll
    for (int q = 0; q < 4; q++)
#pragma unroll
        for (int p = 0; p < 4; p++)
            va[q][p] += ex[(tym + 16 * q) * 32 + txn + 8 * p];

    // ---- epilogue ----
#pragma unroll
    for (int p = 0; p < 4; p++) {
        const int n = n0 + txn + 8 * p;
        float bias = 0.f, scale = 1.f, off = 0.f;
        if (mode == 0) {
            bias  = p0[n];
            scale = p1[n] * rsqrtf(p4[n] + 1e-5f);
            off   = p2[n] - p3[n] * scale;
        } else if (mode == 2) {
            bias = p0[n];
        }
#pragma unroll
        for (int q = 0; q < 4; q++) {
            float v = va[q][p];
            if (mode == 0)      v = fmaxf(fmaf(v + bias, scale, off), 0.f);
            else if (mode == 2) v = v + bias;
            Out[(size_t)(m0 + tym + 16 * q) * N + n] = v;
        }
    }
}

__global__ __launch_bounds__(256)
void k_proj(const float* __restrict__ x,
            const float* __restrict__ W1, const float* __restrict__ b1,
            const float* __restrict__ gam, const float* __restrict__ bet,
            const float* __restrict__ mean, const float* __restrict__ var,
            const float* __restrict__ Wa, const float* __restrict__ Wb,
            const float* __restrict__ bs1)
{
    extern __shared__ __align__(16) float psm[];
    const int m0 = blockIdx.y * 64;
    const int n0 = blockIdx.x * 32;
    const int z  = blockIdx.z;
    if (z == 0)
        gemm64_sk2cp(x, W1, g_H, HIDD, INDIM, m0, n0, 0, b1, gam, bet, mean, var, psm);
    else if (z == 1)
        gemm64_sk2cp(x, Wa, g_A, HIDD, INDIM, m0, n0, 1,
                     nullptr, nullptr, nullptr, nullptr, nullptr, psm);
    else
        gemm64_sk2cp(x, Wb, g_C, HIDD, INDIM, m0, n0, 2,
                     bs1, nullptr, nullptr, nullptr, nullptr, psm);
}

// ============================================================
// H2 split-K2 GEMM tile (R15-proven): 32m x 32n, K=512, 256 thr.
// ============================================================
__device__ __forceinline__ void gemm_h2_sk(
    const float* __restrict__ X, const float* __restrict__ W,
    float* __restrict__ Out, int m0, int n0,
    const float* __restrict__ bias, float* dsm)
{
    const int tid = threadIdx.x;
    const int g   = tid >> 7;
    const int t   = tid & 127;
    const int txn = t & 7;
    const int tym = t >> 3;

    float* Gbase = dsm + g * 6912;
    float* ex    = dsm + 14336;
    const int kb = g * 256;

    const float* srcb[4];
    uint32_t     dsto[4];
#pragma unroll
    for (int r = 0; r < 4; r++) {
        const int p = t + (r << 7);
        if (p < 256) {
            const int row = p >> 3, pc = p & 7;
            srcb[r] = X + (size_t)(m0 + row) * HIDD + kb + pc * 4;
            dsto[r] = (uint32_t)(row * 36 + pc * 4) * 4u;
        } else {
            const int q = p - 256;
            const int row = q >> 3, pc = q & 7;
            srcb[r] = W + (size_t)(n0 + row) * HIDD + kb + pc * 4;
            dsto[r] = (uint32_t)(1152 + row * 36 + pc * 4) * 4u;
        }
    }
    const uint32_t smb = smem_u32(Gbase);

#define H_ISSUE(c) do {                                   \
        const uint32_t sb = smb + ((c) % 3) * 9216u;      \
        CP16(sb + dsto[0], srcb[0] + (c) * 32);           \
        CP16(sb + dsto[1], srcb[1] + (c) * 32);           \
        CP16(sb + dsto[2], srcb[2] + (c) * 32);           \
        CP16(sb + dsto[3], srcb[3] + (c) * 32);           \
        CPCOMMIT();                                       \
    } while (0)

    H_ISSUE(0);
    H_ISSUE(1);

    u64 acc[2][4];
#pragma unroll
    for (int q = 0; q < 2; q++)
#pragma unroll
        for (int p = 0; p < 4; p++) acc[q][p] = 0ull;

#pragma unroll 1
    for (int c = 0; c < 8; ++c) {
        CPWAIT1();
        __syncthreads();
        if (c + 2 < 8) { H_ISSUE(c + 2); } else { CPCOMMIT(); }

        const float* Xb = Gbase + (c % 3) * 2304;
        const float* Wb = Xb + 1152;
#pragma unroll
        for (int k4 = 0; k4 < 32; k4 += 4) {
            ulonglong2 a0 = *(const ulonglong2*)&Xb[(tym +  0) * 36 + k4];
            ulonglong2 a1 = *(const ulonglong2*)&Xb[(tym + 16) * 36 + k4];
            ulonglong2 b0 = *(const ulonglong2*)&Wb[(txn +  0) * 36 + k4];
            ulonglong2 b1 = *(const ulonglong2*)&Wb[(txn +  8) * 36 + k4];
            ulonglong2 b2 = *(const ulonglong2*)&Wb[(txn + 16) * 36 + k4];
            ulonglong2 b3 = *(const ulonglong2*)&Wb[(txn + 24) * 36 + k4];
            acc[0][0] = ffma2(a0.x, b0.x, acc[0][0]); acc[0][0] = ffma2(a0.y, b0.y, acc[0][0]);
            acc[0][1] = ffma2(a0.x, b1.x, acc[0][1]); acc[0][1] = ffma2(a0.y, b1.y, acc[0][1]);
            acc[0][2] = ffma2(a0.x, b2.x, acc[0][2]); acc[0][2] = ffma2(a0.y, b2.y, acc[0][2]);
            acc[0][3] = ffma2(a0.x, b3.x, acc[0][3]); acc[0][3] = ffma2(a0.y, b3.y, acc[0][3]);
            acc[1][0] = ffma2(a1.x, b0.x, acc[1][0]); acc[1][0] = ffma2(a1.y, b0.y, acc[1][0]);
            acc[1][1] = ffma2(a1.x, b1.x, acc[1][1]); acc[1][1] = ffma2(a1.y, b1.y, acc[1][1]);
            acc[1][2] = ffma2(a1.x, b2.x, acc[1][2]); acc[1][2] = ffma2(a1.y, b2.y, acc[1][2]);
            acc[1][3] = ffma2(a1.x, b3.x, acc[1][3]); acc[1][3] = ffma2(a1.y, b3.y, acc[1][3]);
        }
    }
#undef H_ISSUE

    float va[2][4];
#pragma unroll
    for (int q = 0; q < 2; q++)
#pragma unroll
        for (int p = 0; p < 4; p++) {
            float lo, hi; unpack2(acc[q][p], lo, hi);
            va[q][p] = lo + hi;
        }

    if (g == 1) {
        *(float4*)&ex[t * 8]     = make_float4(va[0][0], va[0][1], va[0][2], va[0][3]);
        *(float4*)&ex[t * 8 + 4] = make_float4(va[1][0], va[1][1], va[1][2], va[1][3]);
    }
    __syncthreads();
    if (g == 1) return;
    {
        float4 e0 = *(const float4*)&ex[t * 8];
        float4 e1 = *(const float4*)&ex[t * 8 + 4];
        va[0][0] += e0.x; va[0][1] += e0.y; va[0][2] += e0.z; va[0][3] += e0.w;
        va[1][0] += e1.x; va[1][1] += e1.y; va[1][2] += e1.z; va[1][3] += e1.w;
    }
#pragma unroll
    for (int p = 0; p < 4; p++) {
        const int n = n0 + txn + 8 * p;
        const float b = bias[n];
#pragma unroll
        for (int q = 0; q < 2; q++) {
            const float v = fmaxf(va[q][p] + b, 0.f);
            Out[(size_t)(m0 + tym + 16 * q) * HID2 + n] = v;
        }
    }
}

// ============================================================
// Launch 2 (R15-proven): blocks [0,136) = sim tiles,
// blocks [136,264) = H2 32x32 split-K2 tiles. 256 threads.
// ============================================================
__global__ __launch_bounds__(256)
void k_simh2(const float* __restrict__ W2, const float* __restrict__ b2,
             const float* __restrict__ ws2, const float* __restrict__ bs2p,
             float* __restrict__ out_sim)
{
    extern __shared__ __align__(16) float dsm[];

    if (blockIdx.x >= 136) {
        const int idx = blockIdx.x - 136;          // 0..127
        gemm_h2_sk(g_H, W2, g_H2, (idx >> 3) * 32, (idx & 7) * 32, b2, dsm);
        return;
    }

    const int tid = threadIdx.x;
    const int g   = tid >> 7;
    const int t   = tid & 127;
    const int tx  = t & 7;
    const int ty  = t >> 3;

    float* Gbase = dsm + g * 6912;
    float* Wbuf  = dsm + 13824;
    float* ex    = dsm + 14336;

    int rb = blockIdx.x, bi = 0;
    while (rb >= 16 - bi) { rb -= 16 - bi; ++bi; }
    const int bj = bi + rb;
    const int i0 = bi * 32, j0 = bj * 32;
    const int kb = g * 256;

    const float* srcb[4];
    uint32_t     dsto[4];
#pragma unroll
    for (int r = 0; r < 4; r++) {
        const int p = t + (r << 7);
        if (p < 256) {
            const int row = p >> 3, pc = p & 7;
            srcb[r] = g_A + (size_t)(i0 + row) * HIDD + kb + pc * 4;
            dsto[r] = (uint32_t)(row * 36 + pc * 4) * 4u;
        } else {
            const int q = p - 256;
            const int row = q >> 3, pc = q & 7;
            srcb[r] = g_C + (size_t)(j0 + row) * HIDD + kb + pc * 4;
            dsto[r] = (uint32_t)(1152 + row * 36 + pc * 4) * 4u;
        }
    }
    const uint32_t smb = smem_u32(Gbase);

#define S_ISSUE(c) do {                                   \
        const uint32_t sb = smb + ((c) % 3) * 9216u;      \
        CP16(sb + dsto[0], srcb[0] + (c) * 32);           \
        CP16(sb + dsto[1], srcb[1] + (c) * 32);           \
        CP16(sb + dsto[2], srcb[2] + (c) * 32);           \
        CP16(sb + dsto[3], srcb[3] + (c) * 32);           \
        CPCOMMIT();                                       \
    } while (0)

    S_ISSUE(0);
    S_ISSUE(1);
    if (tid < 128) *(float4*)&Wbuf[tid * 4] = *(const float4*)(ws2 + tid * 4);

    u64 acc2[2][4];
#pragma unroll
    for (int r = 0; r < 2; r++)
#pragma unroll
        for (int p = 0; p < 4; p++) acc2[r][p] = 0ull;

#pragma unroll 1
    for (int c = 0; c < 8; ++c) {
        CPWAIT1();
        __syncthreads();
        if (c + 2 < 8) { S_ISSUE(c + 2); } else { CPCOMMIT(); }

        const float* Ab = Gbase + (c % 3) * 2304;
        const float* Cb = Ab + 1152;
        const float* Wk = Wbuf + kb + c * 32;
#pragma unroll
        for (int k4 = 0; k4 < 32; k4 += 4) {
            ulonglong2 w2  = *(const ulonglong2*)&Wk[k4];
            ulonglong2 aa0 = *(const ulonglong2*)&Ab[(ty +  0) * 36 + k4];
            ulonglong2 aa1 = *(const ulonglong2*)&Ab[(ty + 16) * 36 + k4];
            ulonglong2 cc0 = *(const ulonglong2*)&Cb[(tx +  0) * 36 + k4];
            ulonglong2 cc1 = *(const ulonglong2*)&Cb[(tx +  8) * 36 + k4];
            ulonglong2 cc2 = *(const ulonglong2*)&Cb[(tx + 16) * 36 + k4];
            ulonglong2 cc3 = *(const ulonglong2*)&Cb[(tx + 24) * 36 + k4];
            step2(acc2[0][0], aa0.x, cc0.x, w2.x); step2(acc2[0][0], aa0.y, cc0.y, w2.y);
            step2(acc2[0][1], aa0.x, cc1.x, w2.x); step2(acc2[0][1], aa0.y, cc1.y, w2.y);
            step2(acc2[0][2], aa0.x, cc2.x, w2.x); step2(acc2[0][2], aa0.y, cc2.y, w2.y);
            step2(acc2[0][3], aa0.x, cc3.x, w2.x); step2(acc2[0][3], aa0.y, cc3.y, w2.y);
            step2(acc2[1][0], aa1.x, cc0.x, w2.x); step2(acc2[1][0], aa1.y, cc0.y, w2.y);
            step2(acc2[1][1], aa1.x, cc1.x, w2.x); step2(acc2[1][1], aa1.y, cc1.y, w2.y);
            step2(acc2[1][2], aa1.x, cc2.x, w2.x); step2(acc2[1][2], aa1.y, cc2.y, w2.y);
            step2(acc2[1][3], aa1.x, cc3.x, w2.x); step2(acc2[1][3], aa1.y, cc3.y, w2.y);
        }
    }
#undef S_ISSUE

    float acc[2][4];
#pragma unroll
    for (int r = 0; r < 2; r++)
#pragma unroll
        for (int p = 0; p < 4; p++) {
            float lo, hi; unpack2(acc2[r][p], lo, hi);
            acc[r][p] = lo + hi;
        }

    if (g == 1) {
        *(float4*)&ex[t * 8]     = make_float4(acc[0][0], acc[0][1], acc[0][2], acc[0][3]);
        *(float4*)&ex[t * 8 + 4] = make_float4(acc[1][0], acc[1][1], acc[1][2], acc[1][3]);
    }
    __syncthreads();
    if (g == 1) return;
    {
        float4 e0 = *(const float4*)&ex[t * 8];
        float4 e1 = *(const float4*)&ex[t * 8 + 4];
        acc[0][0] += e0.x; acc[0][1] += e0.y; acc[0][2] += e0.z; acc[0][3] += e0.w;
        acc[1][0] += e1.x; acc[1][1] += e1.y; acc[1][2] += e1.z; acc[1][3] += e1.w;
    }

    const float bs2 = *bs2p;
#pragma unroll
    for (int r = 0; r < 2; r++) {
#pragma unroll
        for (int p = 0; p < 4; p++) {
            const int i = i0 + ty + 16 * r;
            const int j = j0 + tx + 8 * p;
            if (i < j) {
                const float s = 1.f / (1.f + __expf(-(acc[r][p] + bs2)));
                out_sim[(size_t)i * BATCH + j] = s;
                out_sim[(size_t)j * BATCH + i] = s;
            } else if (i == j) {
                out_sim[(size_t)i * BATCH + j] = 0.f;
            }
        }
    }
}

// ============================================================
// Launch 3: scores + softmax. 256 thr = 8 warps (one row each);
// W3 staged in smem once per block (shared by 8 rows).
// ============================================================
__global__ __launch_bounds__(256)
void k_scores(const float* __restrict__ W3, const float* __restrict__ b3,
              float* __restrict__ out_probs, float* __restrict__ out_scores)
{
    __shared__ float w3s[PAT * HID2];

    const int tid  = threadIdx.x;
    for (int i = tid * 4; i < PAT * HID2; i += 256 * 4)
        *(float4*)&w3s[i] = *(const float4*)(W3 + i);
    __syncthreads();

    const int warp = tid >> 5;
    const int lane = tid & 31;
    const int row  = blockIdx.x * 8 + warp;
    const float* h = g_H2 + (size_t)row * HID2;

    float acc[PAT];
#pragma unroll
    for (int p = 0; p < PAT; p++) acc[p] = 0.f;

    for (int k = lane * 4; k < HID2; k += 128) {
        float4 hv = *(const float4*)(h + k);
#pragma unroll
        for (int p = 0; p < PAT; p++) {
            float4 wv = *(const float4*)&w3s[p * HID2 + k];
            acc[p] += hv.x * wv.x + hv.y * wv.y + hv.z * wv.z + hv.w * wv.w;
        }
    }
#pragma unroll
    for (int p = 0; p < PAT; p++) {
#pragma unroll
        for (int off = 16; off; off >>= 1)
            acc[p] += __shfl_xor_sync(0xFFFFFFFFu, acc[p], off);
    }
    if (lane == 0) {
        float s[PAT], e[PAT];
        float mx = -1e30f;
#pragma unroll
        for (int p = 0; p < PAT; p++) { s[p] = acc[p] + b3[p]; mx = fmaxf(mx, s[p]); }
        float sum = 0.f;
#pragma unroll
        for (int p = 0; p < PAT; p++) { e[p] = __expf(s[p] - mx); sum += e[p]; }
        const float inv = 1.f / sum;
#pragma unroll
        for (int p = 0; p < PAT; p++) {
            out_scores[row * PAT + p] = s[p];
            out_probs [row * PAT + p] = e[p] * inv;
        }
    }
}

// ============================================================
extern "C" void kernel_launch(void* const* d_in, const int* in_sizes, int n_in,
                              void* d_out, int out_size)
{
    const float* x    = (const float*)d_in[0];
    const float* W1   = (const float*)d_in[1];
    const float* b1   = (const float*)d_in[2];
    const float* gam  = (const float*)d_in[3];
    const float* bet  = (const float*)d_in[4];
    const float* mean = (const float*)d_in[5];
    const float* var  = (const float*)d_in[6];
    const float* W2   = (const float*)d_in[7];
    const float* b2   = (const float*)d_in[8];
    const float* W3   = (const float*)d_in[9];
    const float* b3   = (const float*)d_in[10];
    const float* Wa   = (const float*)d_in[11];
    const float* Wb   = (const float*)d_in[12];
    const float* bs1  = (const float*)d_in[13];
    const float* ws2  = (const float*)d_in[14];
    const float* bs2  = (const float*)d_in[15];

    float* out        = (float*)d_out;
    float* out_probs  = out;
    float* out_scores = out + BATCH * PAT;
    float* out_sim    = out + 2 * BATCH * PAT;

    static bool attr_done = false;
    if (!attr_done) {
        cudaFuncSetAttribute(k_proj, cudaFuncAttributeMaxDynamicSharedMemorySize,
                             22784 * (int)sizeof(float));
        cudaFuncSetAttribute(k_simh2, cudaFuncAttributeMaxDynamicSharedMemorySize,
                             15360 * (int)sizeof(float));
        attr_done = true;
    }

    // 1) H, A, C projections: 384 CTAs x 256 thr, 64x32 tiles, split-K2 + cp.async
    k_proj<<<dim3(16, 8, 3), 256, 22784 * sizeof(float)>>>(
        x, W1, b1, gam, bet, mean, var, Wa, Wb, bs1);
    // 2) sim (136) + H2 (128, 32x32 split-K2): uniform CTAs (R15-proven)
    k_simh2<<<264, 256, 15360 * sizeof(float)>>>(W2, b2, ws2, bs2, out_sim);
    // 3) scores + softmax (W3 staged in smem)
    k_scores<<<BATCH / 8, 256>>>(W3, b3, out_probs, out_scores);
}